// round 9
// baseline (speedup 1.0000x reference)
#include <cuda_runtime.h>
#include <cstdint>

#define NN 100000
#define EE 1600000
#define NODE_DIM 128
#define HC 32          // heads * channels
#define NHEAD 2
#define NEG_SLOPE 0.2f

// ---------------- scratch (device globals; no allocations allowed) ----------
__device__ float g_xl[NN * HC];
__device__ float g_xr[NN * HC];
__device__ float g_num[NN * HC];
__device__ float g_h[NN * HC];
__device__ float g_den[NN * NHEAD];
__device__ float g_loop[NN];
__device__ float g_deg[NN];
__device__ float g_lsum[NN];

// ---------------- degree / self-loop edge_attr ------------------------------
__global__ void zero_deg_kernel() {
    int i = blockIdx.x * blockDim.x + threadIdx.x;
    if (i < NN) { g_deg[i] = 0.f; g_lsum[i] = 0.f; }
}

__global__ void deg_kernel(const int* __restrict__ dst,
                           const float* __restrict__ eattr) {
    int e = blockIdx.x * blockDim.x + threadIdx.x;
    if (e < EE) {
        int d = dst[e];
        atomicAdd(&g_deg[d], 1.f);
        atomicAdd(&g_lsum[d], eattr[e]);
    }
}

__global__ void loop_kernel() {
    int i = blockIdx.x * blockDim.x + threadIdx.x;
    if (i < NN) g_loop[i] = g_lsum[i] / fmaxf(g_deg[i], 1.f);
}

// ---------------- linear projections: warp per node -------------------------
// xl = in @ Wl + bl ; xr = in @ Wr + br    (W: [D, 32] row-major)
// USE_GH=0: input is the kernel argument x (layer 1, D=128)
// USE_GH=1: input is the device-global g_h (layer 2, D=32) — a __device__
//           symbol must be referenced from DEVICE code, never passed from host.
template <int D, int USE_GH>
__global__ void __launch_bounds__(256) proj_kernel(
    const float* __restrict__ x,
    const float* __restrict__ Wl, const float* __restrict__ bl,
    const float* __restrict__ Wr, const float* __restrict__ br)
{
    int warp = (blockIdx.x * blockDim.x + threadIdx.x) >> 5;
    int lane = threadIdx.x & 31;
    if (warp >= NN) return;
    const float* in = USE_GH ? (const float*)g_h : x;
    const float* xrow = in + (size_t)warp * D;
    float al = __ldg(bl + lane);
    float ar = __ldg(br + lane);
#pragma unroll 8
    for (int k = 0; k < D; k += 4) {
        float4 xv = *(const float4*)(xrow + k);
        al += xv.x * __ldg(Wl + (k + 0) * HC + lane);
        ar += xv.x * __ldg(Wr + (k + 0) * HC + lane);
        al += xv.y * __ldg(Wl + (k + 1) * HC + lane);
        ar += xv.y * __ldg(Wr + (k + 1) * HC + lane);
        al += xv.z * __ldg(Wl + (k + 2) * HC + lane);
        ar += xv.z * __ldg(Wr + (k + 2) * HC + lane);
        al += xv.w * __ldg(Wl + (k + 3) * HC + lane);
        ar += xv.w * __ldg(Wr + (k + 3) * HC + lane);
    }
    g_xl[warp * HC + lane] = al;
    g_xr[warp * HC + lane] = ar;
}

__device__ __forceinline__ float half_reduce16(float t) {
    // sum over 16-lane half-warp (lanes 0-15 and 16-31 independently)
    t += __shfl_xor_sync(0xffffffffu, t, 1);
    t += __shfl_xor_sync(0xffffffffu, t, 2);
    t += __shfl_xor_sync(0xffffffffu, t, 4);
    t += __shfl_xor_sync(0xffffffffu, t, 8);
    return t;
}

// ---------------- self-loop init: num = a_self * xl, den = a_self -----------
__global__ void __launch_bounds__(256) selfinit_kernel(
    const float* __restrict__ We, const float* __restrict__ att)
{
    int n = (blockIdx.x * blockDim.x + threadIdx.x) >> 5;
    int lane = threadIdx.x & 31;
    if (n >= NN) return;
    float xlv = g_xl[n * HC + lane];
    float v = xlv + g_xr[n * HC + lane] + g_loop[n] * __ldg(We + lane);
    v = (v >= 0.f) ? v : NEG_SLOPE * v;
    float t = half_reduce16(v * __ldg(att + lane));   // logit for this head
    float a = __expf(t);
    g_num[n * HC + lane] = a * xlv;
    if ((lane & 15) == 0) g_den[n * NHEAD + (lane >> 4)] = a;
}

// ---------------- edge pass: warp per edge ----------------------------------
__global__ void __launch_bounds__(256) edge_kernel(
    const int* __restrict__ src, const int* __restrict__ dst,
    const float* __restrict__ eattr,
    const float* __restrict__ We, const float* __restrict__ att)
{
    int e = (blockIdx.x * blockDim.x + threadIdx.x) >> 5;
    int lane = threadIdx.x & 31;
    if (e >= EE) return;
    int s = __ldg(src + e);
    int d = __ldg(dst + e);
    float ea = __ldg(eattr + e);
    float xlv = __ldg(&g_xl[s * HC + lane]);          // coalesced 128B line
    float v = xlv + __ldg(&g_xr[d * HC + lane]) + ea * __ldg(We + lane);
    v = (v >= 0.f) ? v : NEG_SLOPE * v;
    float t = half_reduce16(v * __ldg(att + lane));   // per-head logit
    float a = __expf(t);
    atomicAdd(&g_num[d * HC + lane], a * xlv);
    if ((lane & 15) == 0) atomicAdd(&g_den[d * NHEAD + (lane >> 4)], a);
}

// ---------------- finalize: h = num / den + bias ----------------------------
__global__ void __launch_bounds__(256) finalize_kernel(const float* __restrict__ bias)
{
    int i = blockIdx.x * blockDim.x + threadIdx.x;
    if (i >= NN * HC) return;
    int n = i >> 5;
    int l = i & 31;
    g_h[i] = g_num[i] / g_den[n * NHEAD + (l >> 4)] + __ldg(bias + l);
}

// ---------------- decoder: warp per node ------------------------------------
__global__ void __launch_bounds__(256) decoder_kernel(
    const float* __restrict__ Wd1, const float* __restrict__ bd1,
    const float* __restrict__ Wd2, const float* __restrict__ bd2,
    float* __restrict__ out)
{
    int n = (blockIdx.x * blockDim.x + threadIdx.x) >> 5;
    int lane = threadIdx.x & 31;
    if (n >= NN) return;
    float myh = g_h[n * HC + lane];
    float hid = __ldg(bd1 + lane);
#pragma unroll
    for (int k = 0; k < HC; k++) {
        float hv = __shfl_sync(0xffffffffu, myh, k);
        hid += hv * __ldg(Wd1 + k * HC + lane);
    }
    hid = fmaxf(hid, 0.f);
    float o0 = hid * __ldg(Wd2 + lane * 2 + 0);
    float o1 = hid * __ldg(Wd2 + lane * 2 + 1);
#pragma unroll
    for (int m = 16; m > 0; m >>= 1) {
        o0 += __shfl_xor_sync(0xffffffffu, o0, m);
        o1 += __shfl_xor_sync(0xffffffffu, o1, m);
    }
    if (lane == 0) {
        out[n * 2 + 0] = o0 + __ldg(bd2 + 0);
        out[n * 2 + 1] = o1 + __ldg(bd2 + 1);
    }
}

// ---------------- launch ----------------------------------------------------
extern "C" void kernel_launch(void* const* d_in, const int* in_sizes, int n_in,
                              void* d_out, int out_size)
{
    const float* x    = (const float*)d_in[0];
    const int*   ei   = (const int*)  d_in[1];
    const float* ea   = (const float*)d_in[2];
    const float* Wl1  = (const float*)d_in[3];
    const float* bl1  = (const float*)d_in[4];
    const float* Wr1  = (const float*)d_in[5];
    const float* br1  = (const float*)d_in[6];
    const float* We1  = (const float*)d_in[7];
    const float* att1 = (const float*)d_in[8];
    const float* b1   = (const float*)d_in[9];
    const float* Wl2  = (const float*)d_in[10];
    const float* bl2  = (const float*)d_in[11];
    const float* Wr2  = (const float*)d_in[12];
    const float* br2  = (const float*)d_in[13];
    const float* We2  = (const float*)d_in[14];
    const float* att2 = (const float*)d_in[15];
    const float* b2   = (const float*)d_in[16];
    const float* Wd1  = (const float*)d_in[17];
    const float* bd1  = (const float*)d_in[18];
    const float* Wd2  = (const float*)d_in[19];
    const float* bd2  = (const float*)d_in[20];
    float* out = (float*)d_out;

    const int* src = ei;
    const int* dst = ei + EE;

    const int TB = 256;
    int nodeBlocks  = (NN + TB - 1) / TB;           // thread-per-node grids
    int nodeWarpBlk = (NN * 32 + TB - 1) / TB;      // warp-per-node grids
    int edgeBlocks  = (EE + TB - 1) / TB;           // thread-per-edge grids
    int edgeWarpBlk = (EE * 32 + TB - 1) / TB;      // warp-per-edge grids
    int ncBlocks    = (NN * HC + TB - 1) / TB;      // thread-per-(node,col)

    // self-loop attr (shared by both layers)
    zero_deg_kernel<<<nodeBlocks, TB>>>();
    deg_kernel<<<edgeBlocks, TB>>>(dst, ea);
    loop_kernel<<<nodeBlocks, TB>>>();

    // ---- layer 1 ----
    proj_kernel<NODE_DIM, 0><<<nodeWarpBlk, TB>>>(x, Wl1, bl1, Wr1, br1);
    selfinit_kernel<<<nodeWarpBlk, TB>>>(We1, att1);
    edge_kernel<<<edgeWarpBlk, TB>>>(src, dst, ea, We1, att1);
    finalize_kernel<<<ncBlocks, TB>>>(b1);          // -> g_h

    // ---- layer 2 (input g_h read inside the kernel, D=32) ----
    proj_kernel<HC, 1><<<nodeWarpBlk, TB>>>(nullptr, Wl2, bl2, Wr2, br2);
    selfinit_kernel<<<nodeWarpBlk, TB>>>(We2, att2);
    edge_kernel<<<edgeWarpBlk, TB>>>(src, dst, ea, We2, att2);
    finalize_kernel<<<ncBlocks, TB>>>(b2);          // -> g_h (reused)

    // ---- decoder ----
    decoder_kernel<<<nodeWarpBlk, TB>>>(Wd1, bd1, Wd2, bd2, out);
}

// round 10
// speedup vs baseline: 1.2617x; 1.2617x over previous
#include <cuda_runtime.h>
#include <cstdint>

#define NN 100000
#define EE 1600000
#define NODE_DIM 128
#define HC 32          // heads * channels
#define NHEAD 2
#define NEG_SLOPE 0.2f

// ---------------- scratch (device globals; no allocations allowed) ----------
__device__ float g_xl[NN * HC];
__device__ float g_xr[NN * HC];
__device__ float g_num[NN * HC];
__device__ float g_den[NN * NHEAD];
__device__ float g_loop[NN];
__device__ float g_deg[NN];
__device__ float g_lsum[NN];

// ---------------- degree / self-loop edge_attr ------------------------------
__global__ void zero_deg_kernel() {
    int i = blockIdx.x * blockDim.x + threadIdx.x;
    if (i < NN) { g_deg[i] = 0.f; g_lsum[i] = 0.f; }
}

__global__ void deg_kernel(const int* __restrict__ dst,
                           const float* __restrict__ eattr) {
    int e = blockIdx.x * blockDim.x + threadIdx.x;
    if (e < EE) {
        int d = dst[e];
        atomicAdd(&g_deg[d], 1.f);
        atomicAdd(&g_lsum[d], eattr[e]);
    }
}

__global__ void loop_kernel() {
    int i = blockIdx.x * blockDim.x + threadIdx.x;
    if (i < NN) g_loop[i] = g_lsum[i] / fmaxf(g_deg[i], 1.f);
}

// ---------------- tiled projection GEMM --------------------------------------
// C[N x 64] = in[N x D] @ [Wl | Wr]  (+ bl|br), split-stored into g_xl / g_xr.
// SRC=0: in = x argument (layer 1, D=128)
// SRC=1: in[n][k] = g_num[n*32+k] / g_den[n*2+(k>>4)] + bias_in[k]  (fused
//        layer-1 finalize feeding layer-2 projection, D=32)
// Tile: 64 nodes x 64 cols per block, 256 threads, 4x4 register tile/thread.
template <int D, int SRC>
__global__ void __launch_bounds__(256) proj_gemm(
    const float* __restrict__ x, const float* __restrict__ bias_in,
    const float* __restrict__ Wl, const float* __restrict__ bl,
    const float* __restrict__ Wr, const float* __restrict__ br)
{
    __shared__ float Ws[D][64];        // [Wl|Wr] combined
    __shared__ float xs[64][33];       // 64-node x-chunk, padded

    const int tid = threadIdx.x;
    const int node0 = blockIdx.x * 64;

    // load combined weight tile once per block (coalesced within 32-col runs)
    for (int i = tid; i < D * 64; i += 256) {
        int k = i >> 6, c = i & 63;
        Ws[k][c] = (c < 32) ? __ldg(Wl + k * 32 + c) : __ldg(Wr + k * 32 + (c - 32));
    }

    const int c4 = (tid & 15) * 4;     // 4 output cols
    const int ng = tid >> 4;           // node group: 4 nodes
    float acc[4][4];
#pragma unroll
    for (int i = 0; i < 4; i++)
#pragma unroll
        for (int j = 0; j < 4; j++) acc[i][j] = 0.f;

#pragma unroll
    for (int k0 = 0; k0 < D; k0 += 32) {
        __syncthreads();
        // stage 64 nodes x 32 k-values into xs
        if (SRC == 0) {
            // 64 nodes * 8 float4 = 512 float4 loads; 2 per thread, coalesced
#pragma unroll
            for (int it = 0; it < 2; it++) {
                int j = tid + it * 256;            // 0..511
                int n = j >> 3, f = (j & 7) * 4;   // node, float offset
                float4 v = make_float4(0.f, 0.f, 0.f, 0.f);
                int node = node0 + n;
                if (node < NN)
                    v = *(const float4*)(x + (size_t)node * D + k0 + f);
                xs[n][f + 0] = v.x; xs[n][f + 1] = v.y;
                xs[n][f + 2] = v.z; xs[n][f + 3] = v.w;
            }
        } else {
            // fused finalize: h = num/den + bias
#pragma unroll
            for (int it = 0; it < 8; it++) {
                int j = tid + it * 256;            // 0..2047
                int n = j >> 5, k = j & 31;
                int node = node0 + n;
                float v = 0.f;
                if (node < NN)
                    v = g_num[node * HC + k] / g_den[node * NHEAD + (k >> 4)]
                        + __ldg(bias_in + k);
                xs[n][k] = v;
            }
        }
        __syncthreads();

#pragma unroll
        for (int kk = 0; kk < 32; kk++) {
            float4 b = *(const float4*)&Ws[k0 + kk][c4];
            float a0 = xs[ng * 4 + 0][kk];
            float a1 = xs[ng * 4 + 1][kk];
            float a2 = xs[ng * 4 + 2][kk];
            float a3 = xs[ng * 4 + 3][kk];
            acc[0][0] += a0 * b.x; acc[0][1] += a0 * b.y; acc[0][2] += a0 * b.z; acc[0][3] += a0 * b.w;
            acc[1][0] += a1 * b.x; acc[1][1] += a1 * b.y; acc[1][2] += a1 * b.z; acc[1][3] += a1 * b.w;
            acc[2][0] += a2 * b.x; acc[2][1] += a2 * b.y; acc[2][2] += a2 * b.z; acc[2][3] += a2 * b.w;
            acc[3][0] += a3 * b.x; acc[3][1] += a3 * b.y; acc[3][2] += a3 * b.z; acc[3][3] += a3 * b.w;
        }
    }

    // bias + store
    float bv[4];
#pragma unroll
    for (int j = 0; j < 4; j++) {
        int c = c4 + j;
        bv[j] = (c < 32) ? __ldg(bl + c) : __ldg(br + c - 32);
    }
#pragma unroll
    for (int i = 0; i < 4; i++) {
        int node = node0 + ng * 4 + i;
        if (node >= NN) continue;
        float4 v = make_float4(acc[i][0] + bv[0], acc[i][1] + bv[1],
                               acc[i][2] + bv[2], acc[i][3] + bv[3]);
        if (c4 < 32)
            *(float4*)&g_xl[node * HC + c4] = v;
        else
            *(float4*)&g_xr[node * HC + (c4 - 32)] = v;
    }
}

__device__ __forceinline__ float half_reduce16(float t) {
    // sum over 16-lane half-warp (lanes 0-15 and 16-31 independently)
    t += __shfl_xor_sync(0xffffffffu, t, 1);
    t += __shfl_xor_sync(0xffffffffu, t, 2);
    t += __shfl_xor_sync(0xffffffffu, t, 4);
    t += __shfl_xor_sync(0xffffffffu, t, 8);
    return t;
}

// ---------------- self-loop init: num = a_self * xl, den = a_self -----------
__global__ void __launch_bounds__(256) selfinit_kernel(
    const float* __restrict__ We, const float* __restrict__ att)
{
    int n = (blockIdx.x * blockDim.x + threadIdx.x) >> 5;
    int lane = threadIdx.x & 31;
    if (n >= NN) return;
    float xlv = g_xl[n * HC + lane];
    float v = xlv + g_xr[n * HC + lane] + g_loop[n] * __ldg(We + lane);
    v = (v >= 0.f) ? v : NEG_SLOPE * v;
    float t = half_reduce16(v * __ldg(att + lane));   // logit for this head
    float a = __expf(t);
    g_num[n * HC + lane] = a * xlv;
    if ((lane & 15) == 0) g_den[n * NHEAD + (lane >> 4)] = a;
}

// ---------------- edge pass: warp per edge ----------------------------------
__global__ void __launch_bounds__(256) edge_kernel(
    const int* __restrict__ src, const int* __restrict__ dst,
    const float* __restrict__ eattr,
    const float* __restrict__ We, const float* __restrict__ att)
{
    int e = (blockIdx.x * blockDim.x + threadIdx.x) >> 5;
    int lane = threadIdx.x & 31;
    if (e >= EE) return;
    int s = __ldg(src + e);
    int d = __ldg(dst + e);
    float ea = __ldg(eattr + e);
    float xlv = __ldg(&g_xl[s * HC + lane]);          // coalesced 128B line
    float v = xlv + __ldg(&g_xr[d * HC + lane]) + ea * __ldg(We + lane);
    v = (v >= 0.f) ? v : NEG_SLOPE * v;
    float t = half_reduce16(v * __ldg(att + lane));   // per-head logit
    float a = __expf(t);
    atomicAdd(&g_num[d * HC + lane], a * xlv);
    if ((lane & 15) == 0) atomicAdd(&g_den[d * NHEAD + (lane >> 4)], a);
}

// ---------------- decoder (fused layer-2 finalize): warp per node -----------
__global__ void __launch_bounds__(256) decoder_kernel(
    const float* __restrict__ b2,
    const float* __restrict__ Wd1, const float* __restrict__ bd1,
    const float* __restrict__ Wd2, const float* __restrict__ bd2,
    float* __restrict__ out)
{
    int n = (blockIdx.x * blockDim.x + threadIdx.x) >> 5;
    int lane = threadIdx.x & 31;
    if (n >= NN) return;
    float myh = g_num[n * HC + lane] / g_den[n * NHEAD + (lane >> 4)]
                + __ldg(b2 + lane);
    float hid = __ldg(bd1 + lane);
#pragma unroll
    for (int k = 0; k < HC; k++) {
        float hv = __shfl_sync(0xffffffffu, myh, k);
        hid += hv * __ldg(Wd1 + k * HC + lane);
    }
    hid = fmaxf(hid, 0.f);
    float o0 = hid * __ldg(Wd2 + lane * 2 + 0);
    float o1 = hid * __ldg(Wd2 + lane * 2 + 1);
#pragma unroll
    for (int m = 16; m > 0; m >>= 1) {
        o0 += __shfl_xor_sync(0xffffffffu, o0, m);
        o1 += __shfl_xor_sync(0xffffffffu, o1, m);
    }
    if (lane == 0) {
        out[n * 2 + 0] = o0 + __ldg(bd2 + 0);
        out[n * 2 + 1] = o1 + __ldg(bd2 + 1);
    }
}

// ---------------- launch ----------------------------------------------------
extern "C" void kernel_launch(void* const* d_in, const int* in_sizes, int n_in,
                              void* d_out, int out_size)
{
    const float* x    = (const float*)d_in[0];
    const int*   ei   = (const int*)  d_in[1];
    const float* ea   = (const float*)d_in[2];
    const float* Wl1  = (const float*)d_in[3];
    const float* bl1  = (const float*)d_in[4];
    const float* Wr1  = (const float*)d_in[5];
    const float* br1  = (const float*)d_in[6];
    const float* We1  = (const float*)d_in[7];
    const float* att1 = (const float*)d_in[8];
    const float* b1   = (const float*)d_in[9];
    const float* Wl2  = (const float*)d_in[10];
    const float* bl2  = (const float*)d_in[11];
    const float* Wr2  = (const float*)d_in[12];
    const float* br2  = (const float*)d_in[13];
    const float* We2  = (const float*)d_in[14];
    const float* att2 = (const float*)d_in[15];
    const float* b2   = (const float*)d_in[16];
    const float* Wd1  = (const float*)d_in[17];
    const float* bd1  = (const float*)d_in[18];
    const float* Wd2  = (const float*)d_in[19];
    const float* bd2  = (const float*)d_in[20];
    float* out = (float*)d_out;

    const int* src = ei;
    const int* dst = ei + EE;

    const int TB = 256;
    int nodeBlocks  = (NN + TB - 1) / TB;           // thread-per-node grids
    int nodeWarpBlk = (NN * 32 + TB - 1) / TB;      // warp-per-node grids
    int edgeBlocks  = (EE + TB - 1) / TB;           // thread-per-edge grids
    int edgeWarpBlk = (EE * 32 + TB - 1) / TB;      // warp-per-edge grids
    int gemmBlocks  = (NN + 63) / 64;               // 64-node GEMM tiles

    // self-loop attr (shared by both layers)
    zero_deg_kernel<<<nodeBlocks, TB>>>();
    deg_kernel<<<edgeBlocks, TB>>>(dst, ea);
    loop_kernel<<<nodeBlocks, TB>>>();

    // ---- layer 1 ----
    proj_gemm<NODE_DIM, 0><<<gemmBlocks, TB>>>(x, nullptr, Wl1, bl1, Wr1, br1);
    selfinit_kernel<<<nodeWarpBlk, TB>>>(We1, att1);
    edge_kernel<<<edgeWarpBlk, TB>>>(src, dst, ea, We1, att1);

    // ---- layer 2 (finalize1 fused into projection input) ----
    proj_gemm<HC, 1><<<gemmBlocks, TB>>>(nullptr, b1, Wl2, bl2, Wr2, br2);
    selfinit_kernel<<<nodeWarpBlk, TB>>>(We2, att2);
    edge_kernel<<<edgeWarpBlk, TB>>>(src, dst, ea, We2, att2);

    // ---- decoder (finalize2 fused) ----
    decoder_kernel<<<nodeWarpBlk, TB>>>(b2, Wd1, bd1, Wd2, bd2, out);
}

// round 13
// speedup vs baseline: 2.2929x; 1.8174x over previous
#include <cuda_runtime.h>
#include <cstdint>

#define NN 100000
#define EE 1600000
#define NODE_DIM 128
#define HC 32          // heads * channels
#define NHEAD 2
#define NEG_SLOPE 0.2f
#define NB 391         // (NN + 255) / 256  scan blocks

// ---------------- scratch (device globals; no allocations allowed) ----------
__device__ float g_xl[NN * HC];
__device__ float g_xr[NN * HC];
__device__ float g_h[NN * HC];
__device__ int   g_ideg[NN];
__device__ int   g_offs[NN];      // exclusive prefix of in-degree
__device__ int   g_cursor[NN];
__device__ int   g_bsum[512];
__device__ int   g_boff[512];
__device__ int2  g_csr[EE];       // {src, eattr-bits} grouped by dst

// ================= CSR build =================================================
__global__ void zero_ideg_kernel() {
    int i = blockIdx.x * blockDim.x + threadIdx.x;
    if (i < NN) g_ideg[i] = 0;
}

__global__ void hist_kernel(const int* __restrict__ dst) {
    int e = blockIdx.x * blockDim.x + threadIdx.x;
    if (e < EE) atomicAdd(&g_ideg[dst[e]], 1);
}

// per-block sums of in-degree
__global__ void scan1_kernel() {
    __shared__ int s[256];
    int tid = threadIdx.x;
    int i = blockIdx.x * 256 + tid;
    int v = (i < NN) ? g_ideg[i] : 0;
    s[tid] = v;
    __syncthreads();
    for (int off = 128; off > 0; off >>= 1) {
        if (tid < off) s[tid] += s[tid + off];
        __syncthreads();
    }
    if (tid == 0) g_bsum[blockIdx.x] = s[0];
}

// exclusive scan of the NB block sums (one block)
__global__ void scan2_kernel() {
    __shared__ int s[512];
    int tid = threadIdx.x;
    int v = (tid < NB) ? g_bsum[tid] : 0;
    s[tid] = v;
    __syncthreads();
    for (int off = 1; off < 512; off <<= 1) {
        int t = (tid >= off) ? s[tid - off] : 0;
        __syncthreads();
        s[tid] += t;
        __syncthreads();
    }
    g_boff[tid] = s[tid] - v;   // exclusive
}

// in-block exclusive scan + block base -> g_offs; zero cursors
__global__ void scan3_kernel() {
    __shared__ int s[256];
    int tid = threadIdx.x;
    int i = blockIdx.x * 256 + tid;
    int v = (i < NN) ? g_ideg[i] : 0;
    s[tid] = v;
    __syncthreads();
    for (int off = 1; off < 256; off <<= 1) {
        int t = (tid >= off) ? s[tid - off] : 0;
        __syncthreads();
        s[tid] += t;
        __syncthreads();
    }
    if (i < NN) {
        g_offs[i] = s[tid] - v + g_boff[blockIdx.x];
        g_cursor[i] = 0;
    }
}

__global__ void scatter_kernel(const int* __restrict__ src,
                               const int* __restrict__ dst,
                               const float* __restrict__ eattr) {
    int e = blockIdx.x * blockDim.x + threadIdx.x;
    if (e >= EE) return;
    int d = dst[e];
    int pos = g_offs[d] + atomicAdd(&g_cursor[d], 1);
    g_csr[pos] = make_int2(src[e], __float_as_int(eattr[e]));
}

// ================= tiled projection GEMM =====================================
// C[N x 64] = in[N x D] @ [Wl | Wr] (+ bl|br), split-stored into g_xl / g_xr.
// SRC=0: in = x argument (layer 1, D=128); SRC=1: in = g_h (layer 2, D=32).
template <int D, int SRC>
__global__ void __launch_bounds__(256) proj_gemm(
    const float* __restrict__ x,
    const float* __restrict__ Wl, const float* __restrict__ bl,
    const float* __restrict__ Wr, const float* __restrict__ br)
{
    __shared__ float Ws[D][64];
    __shared__ float xs[64][33];

    const int tid = threadIdx.x;
    const int node0 = blockIdx.x * 64;

    for (int i = tid; i < D * 64; i += 256) {
        int k = i >> 6, c = i & 63;
        Ws[k][c] = (c < 32) ? __ldg(Wl + k * 32 + c) : __ldg(Wr + k * 32 + (c - 32));
    }

    const int c4 = (tid & 15) * 4;
    const int ng = tid >> 4;
    float acc[4][4];
#pragma unroll
    for (int i = 0; i < 4; i++)
#pragma unroll
        for (int j = 0; j < 4; j++) acc[i][j] = 0.f;

#pragma unroll
    for (int k0 = 0; k0 < D; k0 += 32) {
        __syncthreads();
        if (SRC == 0) {
#pragma unroll
            for (int it = 0; it < 2; it++) {
                int j = tid + it * 256;
                int n = j >> 3, f = (j & 7) * 4;
                float4 v = make_float4(0.f, 0.f, 0.f, 0.f);
                int node = node0 + n;
                if (node < NN)
                    v = *(const float4*)(x + (size_t)node * D + k0 + f);
                xs[n][f + 0] = v.x; xs[n][f + 1] = v.y;
                xs[n][f + 2] = v.z; xs[n][f + 3] = v.w;
            }
        } else {
#pragma unroll
            for (int it = 0; it < 2; it++) {
                int j = tid + it * 256;
                int n = j >> 3, f = (j & 7) * 4;
                float4 v = make_float4(0.f, 0.f, 0.f, 0.f);
                int node = node0 + n;
                if (node < NN)
                    v = *(const float4*)&g_h[node * HC + f];
                xs[n][f + 0] = v.x; xs[n][f + 1] = v.y;
                xs[n][f + 2] = v.z; xs[n][f + 3] = v.w;
            }
        }
        __syncthreads();

#pragma unroll
        for (int kk = 0; kk < 32; kk++) {
            float4 b = *(const float4*)&Ws[k0 + kk][c4];
            float a0 = xs[ng * 4 + 0][kk];
            float a1 = xs[ng * 4 + 1][kk];
            float a2 = xs[ng * 4 + 2][kk];
            float a3 = xs[ng * 4 + 3][kk];
            acc[0][0] += a0 * b.x; acc[0][1] += a0 * b.y; acc[0][2] += a0 * b.z; acc[0][3] += a0 * b.w;
            acc[1][0] += a1 * b.x; acc[1][1] += a1 * b.y; acc[1][2] += a1 * b.z; acc[1][3] += a1 * b.w;
            acc[2][0] += a2 * b.x; acc[2][1] += a2 * b.y; acc[2][2] += a2 * b.z; acc[2][3] += a2 * b.w;
            acc[3][0] += a3 * b.x; acc[3][1] += a3 * b.y; acc[3][2] += a3 * b.z; acc[3][3] += a3 * b.w;
        }
    }

    float bv[4];
#pragma unroll
    for (int j = 0; j < 4; j++) {
        int c = c4 + j;
        bv[j] = (c < 32) ? __ldg(bl + c) : __ldg(br + c - 32);
    }
#pragma unroll
    for (int i = 0; i < 4; i++) {
        int node = node0 + ng * 4 + i;
        if (node >= NN) continue;
        float4 v = make_float4(acc[i][0] + bv[0], acc[i][1] + bv[1],
                               acc[i][2] + bv[2], acc[i][3] + bv[3]);
        if (c4 < 32)
            *(float4*)&g_xl[node * HC + c4] = v;
        else
            *(float4*)&g_xr[node * HC + (c4 - 32)] = v;
    }
}

__device__ __forceinline__ float half_reduce16(float t) {
    t += __shfl_xor_sync(0xffffffffu, t, 1);
    t += __shfl_xor_sync(0xffffffffu, t, 2);
    t += __shfl_xor_sync(0xffffffffu, t, 4);
    t += __shfl_xor_sync(0xffffffffu, t, 8);
    return t;
}

// ================= CSR aggregation: warp per destination node ================
// Computes self-loop + all incoming edges, softmax-normalized, writes
// h = num/den + bias directly. No atomics, no extra passes.
__global__ void __launch_bounds__(256) agg_kernel(
    const float* __restrict__ We, const float* __restrict__ att,
    const float* __restrict__ bias)
{
    int n = (blockIdx.x * blockDim.x + threadIdx.x) >> 5;
    int lane = threadIdx.x & 31;
    if (n >= NN) return;

    int row0 = g_offs[n];
    int row1 = (n + 1 < NN) ? g_offs[n + 1] : EE;

    // loop_attr = mean of incoming eattr (lane-parallel row sum)
    float es = 0.f;
    for (int i = row0 + lane; i < row1; i += 32)
        es += __int_as_float(g_csr[i].y);
#pragma unroll
    for (int m = 16; m > 0; m >>= 1)
        es += __shfl_xor_sync(0xffffffffu, es, m);
    float loop_attr = es / fmaxf((float)(row1 - row0), 1.f);

    float Wev  = __ldg(We + lane);
    float attv = __ldg(att + lane);
    float xld  = g_xl[n * HC + lane];
    float xrd  = g_xr[n * HC + lane];

    // self loop
    float v = xld + xrd + loop_attr * Wev;
    v = (v >= 0.f) ? v : NEG_SLOPE * v;
    float a = __expf(half_reduce16(v * attv));
    float num = a * xld;
    float den = a;                 // identical within each 16-lane head half

    // incoming edges (prefetch next CSR entry to break the load chain)
    int2 p = (row0 < row1) ? __ldg(&g_csr[row0]) : make_int2(0, 0);
    for (int i = row0; i < row1; ++i) {
        int2 pn = (i + 1 < row1) ? __ldg(&g_csr[i + 1]) : p;
        float xlv = __ldg(&g_xl[p.x * HC + lane]);      // 128B L2 line
        float vv = xlv + xrd + __int_as_float(p.y) * Wev;
        vv = (vv >= 0.f) ? vv : NEG_SLOPE * vv;
        float aa = __expf(half_reduce16(vv * attv));
        num += aa * xlv;
        den += aa;
        p = pn;
    }

    g_h[n * HC + lane] = num / den + __ldg(bias + lane);
}

// ================= decoder: warp per node ====================================
__global__ void __launch_bounds__(256) decoder_kernel(
    const float* __restrict__ Wd1, const float* __restrict__ bd1,
    const float* __restrict__ Wd2, const float* __restrict__ bd2,
    float* __restrict__ out)
{
    int n = (blockIdx.x * blockDim.x + threadIdx.x) >> 5;
    int lane = threadIdx.x & 31;
    if (n >= NN) return;
    float myh = g_h[n * HC + lane];
    float hid = __ldg(bd1 + lane);
#pragma unroll
    for (int k = 0; k < HC; k++) {
        float hv = __shfl_sync(0xffffffffu, myh, k);
        hid += hv * __ldg(Wd1 + k * HC + lane);
    }
    hid = fmaxf(hid, 0.f);
    float o0 = hid * __ldg(Wd2 + lane * 2 + 0);
    float o1 = hid * __ldg(Wd2 + lane * 2 + 1);
#pragma unroll
    for (int m = 16; m > 0; m >>= 1) {
        o0 += __shfl_xor_sync(0xffffffffu, o0, m);
        o1 += __shfl_xor_sync(0xffffffffu, o1, m);
    }
    if (lane == 0) {
        out[n * 2 + 0] = o0 + __ldg(bd2 + 0);
        out[n * 2 + 1] = o1 + __ldg(bd2 + 1);
    }
}

// ================= launch ====================================================
extern "C" void kernel_launch(void* const* d_in, const int* in_sizes, int n_in,
                              void* d_out, int out_size)
{
    const float* x    = (const float*)d_in[0];
    const int*   ei   = (const int*)  d_in[1];
    const float* ea   = (const float*)d_in[2];
    const float* Wl1  = (const float*)d_in[3];
    const float* bl1  = (const float*)d_in[4];
    const float* Wr1  = (const float*)d_in[5];
    const float* br1  = (const float*)d_in[6];
    const float* We1  = (const float*)d_in[7];
    const float* att1 = (const float*)d_in[8];
    const float* b1   = (const float*)d_in[9];
    const float* Wl2  = (const float*)d_in[10];
    const float* bl2  = (const float*)d_in[11];
    const float* Wr2  = (const float*)d_in[12];
    const float* br2  = (const float*)d_in[13];
    const float* We2  = (const float*)d_in[14];
    const float* att2 = (const float*)d_in[15];
    const float* b2   = (const float*)d_in[16];
    const float* Wd1  = (const float*)d_in[17];
    const float* bd1  = (const float*)d_in[18];
    const float* Wd2  = (const float*)d_in[19];
    const float* bd2  = (const float*)d_in[20];
    float* out = (float*)d_out;

    const int* src = ei;
    const int* dst = ei + EE;

    const int TB = 256;
    int nodeBlocks  = (NN + TB - 1) / TB;           // = NB
    int edgeBlocks  = (EE + TB - 1) / TB;
    int nodeWarpBlk = (NN * 32 + TB - 1) / TB;
    int gemmBlocks  = (NN + 63) / 64;

    // ---- CSR build (shared by both layers) ----
    zero_ideg_kernel<<<nodeBlocks, TB>>>();
    hist_kernel<<<edgeBlocks, TB>>>(dst);
    scan1_kernel<<<NB, 256>>>();
    scan2_kernel<<<1, 512>>>();
    scan3_kernel<<<NB, 256>>>();
    scatter_kernel<<<edgeBlocks, TB>>>(src, dst, ea);

    // ---- layer 1 ----
    proj_gemm<NODE_DIM, 0><<<gemmBlocks, TB>>>(x, Wl1, bl1, Wr1, br1);
    agg_kernel<<<nodeWarpBlk, TB>>>(We1, att1, b1);

    // ---- layer 2 (reads g_h inside proj) ----
    proj_gemm<HC, 1><<<gemmBlocks, TB>>>(nullptr, Wl2, bl2, Wr2, br2);
    agg_kernel<<<nodeWarpBlk, TB>>>(We2, att2, b2);

    // ---- decoder ----
    decoder_kernel<<<nodeWarpBlk, TB>>>(Wd1, bd1, Wd2, bd2, out);
}

// round 14
// speedup vs baseline: 2.2932x; 1.0001x over previous
#include <cuda_runtime.h>
#include <cstdint>

#define NN 100000
#define EE 1600000
#define NODE_DIM 128
#define HC 32          // heads * channels
#define NHEAD 2
#define NEG_SLOPE 0.2f
#define NB 391         // (NN + 255) / 256  scan blocks

// ---------------- scratch (device globals; no allocations allowed) ----------
__device__ float g_xl[NN * HC];
__device__ float g_xr[NN * HC];
__device__ float g_h[NN * HC];
__device__ int   g_ideg[NN];
__device__ int   g_offs[NN];      // exclusive prefix of in-degree
__device__ int   g_cursor[NN];
__device__ int   g_bsum[512];
__device__ int   g_boff[512];
__device__ int2  g_csr[EE];       // {src, eattr-bits} grouped by dst

// ================= CSR build =================================================
__global__ void zero_ideg_kernel() {
    int i = blockIdx.x * blockDim.x + threadIdx.x;
    if (i < NN) g_ideg[i] = 0;
}

__global__ void hist_kernel(const int* __restrict__ dst) {
    int e = blockIdx.x * blockDim.x + threadIdx.x;
    if (e < EE) atomicAdd(&g_ideg[dst[e]], 1);
}

// per-block sums of in-degree
__global__ void scan1_kernel() {
    __shared__ int s[256];
    int tid = threadIdx.x;
    int i = blockIdx.x * 256 + tid;
    int v = (i < NN) ? g_ideg[i] : 0;
    s[tid] = v;
    __syncthreads();
    for (int off = 128; off > 0; off >>= 1) {
        if (tid < off) s[tid] += s[tid + off];
        __syncthreads();
    }
    if (tid == 0) g_bsum[blockIdx.x] = s[0];
}

// exclusive scan of the NB block sums (one block)
__global__ void scan2_kernel() {
    __shared__ int s[512];
    int tid = threadIdx.x;
    int v = (tid < NB) ? g_bsum[tid] : 0;
    s[tid] = v;
    __syncthreads();
    for (int off = 1; off < 512; off <<= 1) {
        int t = (tid >= off) ? s[tid - off] : 0;
        __syncthreads();
        s[tid] += t;
        __syncthreads();
    }
    g_boff[tid] = s[tid] - v;   // exclusive
}

// in-block exclusive scan + block base -> g_offs; zero cursors
__global__ void scan3_kernel() {
    __shared__ int s[256];
    int tid = threadIdx.x;
    int i = blockIdx.x * 256 + tid;
    int v = (i < NN) ? g_ideg[i] : 0;
    s[tid] = v;
    __syncthreads();
    for (int off = 1; off < 256; off <<= 1) {
        int t = (tid >= off) ? s[tid - off] : 0;
        __syncthreads();
        s[tid] += t;
        __syncthreads();
    }
    if (i < NN) {
        g_offs[i] = s[tid] - v + g_boff[blockIdx.x];
        g_cursor[i] = 0;
    }
}

__global__ void scatter_kernel(const int* __restrict__ src,
                               const int* __restrict__ dst,
                               const float* __restrict__ eattr) {
    int e = blockIdx.x * blockDim.x + threadIdx.x;
    if (e >= EE) return;
    int d = dst[e];
    int pos = g_offs[d] + atomicAdd(&g_cursor[d], 1);
    g_csr[pos] = make_int2(src[e], __float_as_int(eattr[e]));
}

// ================= tiled projection GEMM =====================================
// C[N x 64] = in[N x D] @ [Wl | Wr] (+ bl|br), split-stored into g_xl / g_xr.
// SRC=0: in = x argument (layer 1, D=128); SRC=1: in = g_h (layer 2, D=32).
template <int D, int SRC>
__global__ void __launch_bounds__(256) proj_gemm(
    const float* __restrict__ x,
    const float* __restrict__ Wl, const float* __restrict__ bl,
    const float* __restrict__ Wr, const float* __restrict__ br)
{
    __shared__ float Ws[D][64];
    __shared__ float xs[64][33];

    const int tid = threadIdx.x;
    const int node0 = blockIdx.x * 64;

    for (int i = tid; i < D * 64; i += 256) {
        int k = i >> 6, c = i & 63;
        Ws[k][c] = (c < 32) ? __ldg(Wl + k * 32 + c) : __ldg(Wr + k * 32 + (c - 32));
    }

    const int c4 = (tid & 15) * 4;
    const int ng = tid >> 4;
    float acc[4][4];
#pragma unroll
    for (int i = 0; i < 4; i++)
#pragma unroll
        for (int j = 0; j < 4; j++) acc[i][j] = 0.f;

#pragma unroll
    for (int k0 = 0; k0 < D; k0 += 32) {
        __syncthreads();
        if (SRC == 0) {
#pragma unroll
            for (int it = 0; it < 2; it++) {
                int j = tid + it * 256;
                int n = j >> 3, f = (j & 7) * 4;
                float4 v = make_float4(0.f, 0.f, 0.f, 0.f);
                int node = node0 + n;
                if (node < NN)
                    v = *(const float4*)(x + (size_t)node * D + k0 + f);
                xs[n][f + 0] = v.x; xs[n][f + 1] = v.y;
                xs[n][f + 2] = v.z; xs[n][f + 3] = v.w;
            }
        } else {
#pragma unroll
            for (int it = 0; it < 2; it++) {
                int j = tid + it * 256;
                int n = j >> 3, f = (j & 7) * 4;
                float4 v = make_float4(0.f, 0.f, 0.f, 0.f);
                int node = node0 + n;
                if (node < NN)
                    v = *(const float4*)&g_h[node * HC + f];
                xs[n][f + 0] = v.x; xs[n][f + 1] = v.y;
                xs[n][f + 2] = v.z; xs[n][f + 3] = v.w;
            }
        }
        __syncthreads();

#pragma unroll
        for (int kk = 0; kk < 32; kk++) {
            float4 b = *(const float4*)&Ws[k0 + kk][c4];
            float a0 = xs[ng * 4 + 0][kk];
            float a1 = xs[ng * 4 + 1][kk];
            float a2 = xs[ng * 4 + 2][kk];
            float a3 = xs[ng * 4 + 3][kk];
            acc[0][0] += a0 * b.x; acc[0][1] += a0 * b.y; acc[0][2] += a0 * b.z; acc[0][3] += a0 * b.w;
            acc[1][0] += a1 * b.x; acc[1][1] += a1 * b.y; acc[1][2] += a1 * b.z; acc[1][3] += a1 * b.w;
            acc[2][0] += a2 * b.x; acc[2][1] += a2 * b.y; acc[2][2] += a2 * b.z; acc[2][3] += a2 * b.w;
            acc[3][0] += a3 * b.x; acc[3][1] += a3 * b.y; acc[3][2] += a3 * b.z; acc[3][3] += a3 * b.w;
        }
    }

    float bv[4];
#pragma unroll
    for (int j = 0; j < 4; j++) {
        int c = c4 + j;
        bv[j] = (c < 32) ? __ldg(bl + c) : __ldg(br + c - 32);
    }
#pragma unroll
    for (int i = 0; i < 4; i++) {
        int node = node0 + ng * 4 + i;
        if (node >= NN) continue;
        float4 v = make_float4(acc[i][0] + bv[0], acc[i][1] + bv[1],
                               acc[i][2] + bv[2], acc[i][3] + bv[3]);
        if (c4 < 32)
            *(float4*)&g_xl[node * HC + c4] = v;
        else
            *(float4*)&g_xr[node * HC + (c4 - 32)] = v;
    }
}

__device__ __forceinline__ float half_reduce16(float t) {
    t += __shfl_xor_sync(0xffffffffu, t, 1);
    t += __shfl_xor_sync(0xffffffffu, t, 2);
    t += __shfl_xor_sync(0xffffffffu, t, 4);
    t += __shfl_xor_sync(0xffffffffu, t, 8);
    return t;
}

// ================= CSR aggregation: warp per destination node ================
// Computes self-loop + all incoming edges, softmax-normalized, writes
// h = num/den + bias directly. No atomics, no extra passes.
__global__ void __launch_bounds__(256) agg_kernel(
    const float* __restrict__ We, const float* __restrict__ att,
    const float* __restrict__ bias)
{
    int n = (blockIdx.x * blockDim.x + threadIdx.x) >> 5;
    int lane = threadIdx.x & 31;
    if (n >= NN) return;

    int row0 = g_offs[n];
    int row1 = (n + 1 < NN) ? g_offs[n + 1] : EE;

    // loop_attr = mean of incoming eattr (lane-parallel row sum)
    float es = 0.f;
    for (int i = row0 + lane; i < row1; i += 32)
        es += __int_as_float(g_csr[i].y);
#pragma unroll
    for (int m = 16; m > 0; m >>= 1)
        es += __shfl_xor_sync(0xffffffffu, es, m);
    float loop_attr = es / fmaxf((float)(row1 - row0), 1.f);

    float Wev  = __ldg(We + lane);
    float attv = __ldg(att + lane);
    float xld  = g_xl[n * HC + lane];
    float xrd  = g_xr[n * HC + lane];

    // self loop
    float v = xld + xrd + loop_attr * Wev;
    v = (v >= 0.f) ? v : NEG_SLOPE * v;
    float a = __expf(half_reduce16(v * attv));
    float num = a * xld;
    float den = a;                 // identical within each 16-lane head half

    // incoming edges (prefetch next CSR entry to break the load chain)
    int2 p = (row0 < row1) ? __ldg(&g_csr[row0]) : make_int2(0, 0);
    for (int i = row0; i < row1; ++i) {
        int2 pn = (i + 1 < row1) ? __ldg(&g_csr[i + 1]) : p;
        float xlv = __ldg(&g_xl[p.x * HC + lane]);      // 128B L2 line
        float vv = xlv + xrd + __int_as_float(p.y) * Wev;
        vv = (vv >= 0.f) ? vv : NEG_SLOPE * vv;
        float aa = __expf(half_reduce16(vv * attv));
        num += aa * xlv;
        den += aa;
        p = pn;
    }

    g_h[n * HC + lane] = num / den + __ldg(bias + lane);
}

// ================= decoder: warp per node ====================================
__global__ void __launch_bounds__(256) decoder_kernel(
    const float* __restrict__ Wd1, const float* __restrict__ bd1,
    const float* __restrict__ Wd2, const float* __restrict__ bd2,
    float* __restrict__ out)
{
    int n = (blockIdx.x * blockDim.x + threadIdx.x) >> 5;
    int lane = threadIdx.x & 31;
    if (n >= NN) return;
    float myh = g_h[n * HC + lane];
    float hid = __ldg(bd1 + lane);
#pragma unroll
    for (int k = 0; k < HC; k++) {
        float hv = __shfl_sync(0xffffffffu, myh, k);
        hid += hv * __ldg(Wd1 + k * HC + lane);
    }
    hid = fmaxf(hid, 0.f);
    float o0 = hid * __ldg(Wd2 + lane * 2 + 0);
    float o1 = hid * __ldg(Wd2 + lane * 2 + 1);
#pragma unroll
    for (int m = 16; m > 0; m >>= 1) {
        o0 += __shfl_xor_sync(0xffffffffu, o0, m);
        o1 += __shfl_xor_sync(0xffffffffu, o1, m);
    }
    if (lane == 0) {
        out[n * 2 + 0] = o0 + __ldg(bd2 + 0);
        out[n * 2 + 1] = o1 + __ldg(bd2 + 1);
    }
}

// ================= launch ====================================================
extern "C" void kernel_launch(void* const* d_in, const int* in_sizes, int n_in,
                              void* d_out, int out_size)
{
    const float* x    = (const float*)d_in[0];
    const int*   ei   = (const int*)  d_in[1];
    const float* ea   = (const float*)d_in[2];
    const float* Wl1  = (const float*)d_in[3];
    const float* bl1  = (const float*)d_in[4];
    const float* Wr1  = (const float*)d_in[5];
    const float* br1  = (const float*)d_in[6];
    const float* We1  = (const float*)d_in[7];
    const float* att1 = (const float*)d_in[8];
    const float* b1   = (const float*)d_in[9];
    const float* Wl2  = (const float*)d_in[10];
    const float* bl2  = (const float*)d_in[11];
    const float* Wr2  = (const float*)d_in[12];
    const float* br2  = (const float*)d_in[13];
    const float* We2  = (const float*)d_in[14];
    const float* att2 = (const float*)d_in[15];
    const float* b2   = (const float*)d_in[16];
    const float* Wd1  = (const float*)d_in[17];
    const float* bd1  = (const float*)d_in[18];
    const float* Wd2  = (const float*)d_in[19];
    const float* bd2  = (const float*)d_in[20];
    float* out = (float*)d_out;

    const int* src = ei;
    const int* dst = ei + EE;

    const int TB = 256;
    int nodeBlocks  = (NN + TB - 1) / TB;           // = NB
    int edgeBlocks  = (EE + TB - 1) / TB;
    int nodeWarpBlk = (NN * 32 + TB - 1) / TB;
    int gemmBlocks  = (NN + 63) / 64;

    // ---- CSR build (shared by both layers) ----
    zero_ideg_kernel<<<nodeBlocks, TB>>>();
    hist_kernel<<<edgeBlocks, TB>>>(dst);
    scan1_kernel<<<NB, 256>>>();
    scan2_kernel<<<1, 512>>>();
    scan3_kernel<<<NB, 256>>>();
    scatter_kernel<<<edgeBlocks, TB>>>(src, dst, ea);

    // ---- layer 1 ----
    proj_gemm<NODE_DIM, 0><<<gemmBlocks, TB>>>(x, Wl1, bl1, Wr1, br1);
    agg_kernel<<<nodeWarpBlk, TB>>>(We1, att1, b1);

    // ---- layer 2 (reads g_h inside proj) ----
    proj_gemm<HC, 1><<<gemmBlocks, TB>>>(nullptr, Wl2, bl2, Wr2, br2);
    agg_kernel<<<nodeWarpBlk, TB>>>(We2, att2, b2);

    // ---- decoder ----
    decoder_kernel<<<nodeWarpBlk, TB>>>(Wd1, bd1, Wd2, bd2, out);
}